// round 14
// baseline (speedup 1.0000x reference)
#include <cuda_runtime.h>
#include <cuda_fp16.h>
#include <math.h>
#include <stdint.h>

#define N_ATOMS   100000
#define ATOM_FDIM 133
#define KPAD_F    160
#define HIDDEN    512
#define K_CAT     (KPAD_F + HIDDEN)   // 672
#define MAX_NEI   6
#define N_MOLS    4096
#define N_PAIRS   8192
#define FFN1      2048
#define FFN2      1024

#define MODE_N    0
#define MODE_PAIR 2
#define MODE_DOT  3

// ---------------- scratch (device globals: allocation-free) ----------------
__device__ alignas(16) __half g_padAh [N_ATOMS * KPAD_F];
__device__ alignas(16) __half g_inph  [N_ATOMS * HIDDEN];
__device__ alignas(16) __half g_bufBh [N_ATOMS * HIDDEN];
__device__ alignas(16) __half g_bufCh [N_ATOMS * HIDDEN];
__device__ alignas(16) __half g_h1h   [N_PAIRS * FFN1];
__device__ alignas(16) __half g_prodh [N_PAIRS * HIDDEN];
__device__ alignas(16) __half g_mvh   [N_MOLS * HIDDEN];
__device__ alignas(16) __half g_Uh    [N_MOLS * 4096];
__device__ float g_dot [N_PAIRS];
__device__ float g_sums[N_MOLS * HIDDEN];
__device__ float g_cnt [N_MOLS];
__device__ int   g_segStart[N_MOLS + 1];
// transposed half weights [N][K] (K-contiguous)
__device__ alignas(16) __half g_WiTh   [HIDDEN * KPAD_F];
__device__ alignas(16) __half g_WoCatTh[HIDDEN * K_CAT];
__device__ alignas(16) __half g_WhTh   [HIDDEN * HIDDEN];
__device__ alignas(16) __half g_WcombTh[4096 * HIDDEN];
__device__ alignas(16) __half g_WmTh   [FFN1 * HIDDEN];
__device__ alignas(16) __half g_Wf1Th  [FFN2 * FFN1];

// ---------------- PTX helpers ----------------------------------------------
__device__ __forceinline__ uint32_t smem_u32(const void* p) {
    return (uint32_t)__cvta_generic_to_shared(p);
}
__device__ __forceinline__ void cp16(uint32_t s, const void* g, uint32_t bytes) {
    asm volatile("cp.async.cg.shared.global [%0], [%1], 16, %2;\n"
                 :: "r"(s), "l"(g), "r"(bytes));
}
__device__ __forceinline__ void cp_commit() {
    asm volatile("cp.async.commit_group;\n" ::: "memory");
}
template <int N>
__device__ __forceinline__ void cp_wait() {
    asm volatile("cp.async.wait_group %0;\n" :: "n"(N) : "memory");
}
__device__ __forceinline__ void ldsm4(uint32_t* r, uint32_t addr) {
    asm volatile("ldmatrix.sync.aligned.m8n8.x4.shared.b16 {%0,%1,%2,%3}, [%4];\n"
                 : "=r"(r[0]), "=r"(r[1]), "=r"(r[2]), "=r"(r[3]) : "r"(addr));
}
__device__ __forceinline__ void mma_f16(float* c, const uint32_t* a,
                                        uint32_t b0, uint32_t b1) {
    asm volatile(
        "mma.sync.aligned.m16n8k16.row.col.f32.f16.f16.f32 "
        "{%0,%1,%2,%3}, {%4,%5,%6,%7}, {%8,%9}, {%0,%1,%2,%3};\n"
        : "+f"(c[0]), "+f"(c[1]), "+f"(c[2]), "+f"(c[3])
        : "r"(a[0]), "r"(a[1]), "r"(a[2]), "r"(a[3]), "r"(b0), "r"(b1));
}

// ---------------- GEMM tile config ------------------------------------------
#define BM 128
#define BN 64
#define BK 32
#define STAGES 4
#define AT 40
#define A_H (BM * AT)                         // 5120 halves
#define B_H (BN * AT)                         // 2560 halves
#define STAGE_H (A_H + B_H)                   // 7680
#define STAGE_BYTES (STAGE_H * 2)             // 15360
#define SMEM_BYTES (STAGES * STAGE_BYTES)     // 61440

// ---------------- fp16 mma GEMM: C = [A1|A2][MxK] @ BT[NxK]^T ---------------
// 256 threads, 8 warps in 4x2 grid, warp tile 32x32, 3 CTAs/SM target.
template <int MODE, bool RELU, bool ADDC, bool CINH, bool BIAS, bool OUTH>
__global__ __launch_bounds__(256, 3)
void hgemm(int M, int N, int K, int K1, int lda1, int lda2, int ldb,
           int ldcin, int ldc,
           const __half* __restrict__ A1, const __half* __restrict__ A2,
           const __half* __restrict__ BT,
           const void* __restrict__ Cin, const float* __restrict__ bias,
           void* __restrict__ Cout,
           const int* __restrict__ idx, const void* __restrict__ Uv)
{
    extern __shared__ __half sm[];
    const uint32_t sbase = smem_u32(sm);
    const int tid = threadIdx.x;
    const int lane = tid & 31, wid = tid >> 5;
    const int wm = wid & 3, wn = wid >> 2;     // 4 x 2, warp tile 32x32
    const int gid = lane >> 2, tig = lane & 3;
    const int rowBase = blockIdx.y * BM;
    const int colBase = blockIdx.x * BN;
    const int nk = K / BK;

    // A tile: 128 rows x 32 halves -> 512 cp16, 2/thread.
    // B tile: 64 rows x 32 halves -> 256 cp16, 1/thread.
    const __half* aPtr1[2]; const __half* aPtr2[2];
    uint32_t aSm[2]; uint32_t aBytes[2];
#pragma unroll
    for (int j = 0; j < 2; j++) {
        int idx2 = tid + j * 256;
        int row = idx2 >> 2, c = idx2 & 3;
        int grow = rowBase + row;
        int crow = grow < M ? grow : 0;
        aPtr1[j]  = A1 + (size_t)crow * lda1 + c * 8;
        aPtr2[j]  = A2 + (size_t)crow * lda2 + c * 8;
        aSm[j]    = sbase + (uint32_t)(row * AT + c * 8) * 2;
        aBytes[j] = grow < M ? 16u : 0u;
    }
    const __half* bPtr;
    uint32_t bSm;
    {
        int row = tid >> 2, c = tid & 3;
        bPtr = BT + (size_t)(colBase + row) * ldb + c * 8;
        bSm  = sbase + (uint32_t)(A_H + row * AT + c * 8) * 2;
    }

    auto load_stage = [&](int stg, int kc0) {
        const uint32_t so = (uint32_t)stg * STAGE_BYTES;
#pragma unroll
        for (int j = 0; j < 2; j++) {
            const __half* src = (kc0 < K1) ? (aPtr1[j] + kc0)
                                           : (aPtr2[j] + (kc0 - K1));
            cp16(aSm[j] + so, src, aBytes[j]);
        }
        cp16(bSm + so, bPtr + kc0, 16u);
        cp_commit();
    };

    const int lr = lane & 15, lc = lane >> 4;
    uint32_t aLd[2], bLd[2];
#pragma unroll
    for (int mt = 0; mt < 2; mt++)
        aLd[mt] = sbase + (uint32_t)((wm * 32 + mt * 16 + lr) * AT + lc * 8) * 2;
#pragma unroll
    for (int j = 0; j < 2; j++)
        bLd[j] = sbase + (uint32_t)(A_H + (wn * 32 + j * 16 + lr) * AT + lc * 8) * 2;

    float acc[2][4][4];
#pragma unroll
    for (int mt = 0; mt < 2; mt++)
#pragma unroll
        for (int nt = 0; nt < 4; nt++)
#pragma unroll
            for (int i = 0; i < 4; i++) acc[mt][nt][i] = 0.f;

    load_stage(0, 0);
    if (nk > 1) load_stage(1, BK);
    if (nk > 2) load_stage(2, 2 * BK);

    int buf = 0;
    for (int kt = 0; kt < nk; kt++) {
        if (kt == nk - 1)      cp_wait<0>();
        else if (kt == nk - 2) cp_wait<1>();
        else                   cp_wait<2>();
        __syncthreads();
        if (kt + 3 < nk)
            load_stage((buf + 3) % STAGES, (kt + 3) * BK);

        const uint32_t so = (uint32_t)buf * STAGE_BYTES;
#pragma unroll
        for (int ks = 0; ks < 2; ks++) {
            const uint32_t ko = so + ks * 32;
            uint32_t af[2][4], bf[2][4];
            ldsm4(af[0], aLd[0] + ko);
            ldsm4(af[1], aLd[1] + ko);
            ldsm4(bf[0], bLd[0] + ko);
            ldsm4(bf[1], bLd[1] + ko);
#pragma unroll
            for (int mt = 0; mt < 2; mt++)
#pragma unroll
                for (int j = 0; j < 2; j++) {
                    mma_f16(acc[mt][2 * j],     af[mt], bf[j][0], bf[j][2]);
                    mma_f16(acc[mt][2 * j + 1], af[mt], bf[j][1], bf[j][3]);
                }
        }
        buf = (buf + 1) % STAGES;
    }

    // ---- epilogue ----
#pragma unroll
    for (int mt = 0; mt < 2; mt++) {
#pragma unroll
        for (int h = 0; h < 2; h++) {
            const int row = rowBase + wm * 32 + mt * 16 + gid + h * 8;
            if (row >= M) continue;
            int e0 = 0, e1 = 0;
            if (MODE == MODE_PAIR) { e0 = __ldg(&idx[row]); e1 = __ldg(&idx[N_PAIRS + row]); }
            float dpart = 0.f;
#pragma unroll
            for (int nt = 0; nt < 4; nt++) {
                const int gc = colBase + wn * 32 + nt * 8 + tig * 2;
                float2 v = make_float2(acc[mt][nt][2 * h], acc[mt][nt][2 * h + 1]);
                if (BIAS) {
                    const float2 bb = *(const float2*)(bias + gc);
                    v.x += bb.x; v.y += bb.y;
                }
                if (ADDC) {
                    float2 ci;
                    if (CINH) {
                        __half2 c2 = *(const __half2*)((const __half*)Cin + (size_t)row * ldcin + gc);
                        ci = __half22float2(c2);
                    } else {
                        ci = *(const float2*)((const float*)Cin + (size_t)row * ldcin + gc);
                    }
                    v.x += ci.x; v.y += ci.y;
                }
                if (MODE == MODE_PAIR) {
                    const __half* Uhp = (const __half*)Uv;
                    float2 u1 = __half22float2(*(const __half2*)(Uhp + (size_t)e0 * 4096 + gc));
                    float2 u2 = __half22float2(*(const __half2*)(Uhp + (size_t)e1 * 4096 + FFN1 + gc));
                    v.x += u1.x + u2.x; v.y += u1.y + u2.y;
                }
                if (RELU) { v.x = fmaxf(v.x, 0.f); v.y = fmaxf(v.y, 0.f); }
                if (MODE == MODE_DOT) {
                    const float2 w2 = *(const float2*)((const float*)Uv + gc);
                    dpart += v.x * w2.x + v.y * w2.y;
                } else if (OUTH) {
                    *(__half2*)((__half*)Cout + (size_t)row * ldc + gc) = __floats2half2_rn(v.x, v.y);
                } else {
                    *(float2*)((float*)Cout + (size_t)row * ldc + gc) = v;
                }
            }
            if (MODE == MODE_DOT) {
                dpart += __shfl_xor_sync(0xffffffffu, dpart, 1);
                dpart += __shfl_xor_sync(0xffffffffu, dpart, 2);
                if (tig == 0) atomicAdd((float*)Cout + row, dpart);
            }
        }
    }
}

// ---------------- mega prep: all weight prep + pad + seg bounds, 1 launch ----
#define PB_PAD    62500
#define PB_WIT    (PB_PAD + (HIDDEN / 32) * (KPAD_F / 32))
#define PB_WOCAT  (PB_WIT + (HIDDEN * K_CAT) / 256)
#define PB_WH     (PB_WOCAT + (HIDDEN / 32) * (HIDDEN / 32))
#define PB_WCOMB  (PB_WH + (4096 * HIDDEN) / 256)
#define PB_WM     (PB_WCOMB + (FFN1 / 32) * (HIDDEN / 32))
#define PB_WF1    (PB_WM + (FFN2 / 32) * (FFN1 / 32))
#define PB_SEG    (PB_WF1 + 17)
#define PREP_BLOCKS PB_SEG

__device__ __forceinline__ void tile_transpose(const float* __restrict__ W,
                                               __half* __restrict__ WT,
                                               int K, int N, int Kpad,
                                               int bx, int by, int tid,
                                               float (*t)[33])
{
    int kb = by * 32, nb = bx * 32;
    int tx = tid & 31, ty = tid >> 5;
#pragma unroll
    for (int i = 0; i < 4; i++) {
        int kk = kb + ty + i * 8;
        t[ty + i * 8][tx] = (kk < K) ? W[(size_t)kk * N + nb + tx] : 0.f;
    }
    __syncthreads();
#pragma unroll
    for (int i = 0; i < 4; i++) {
        int n = nb + ty + i * 8;
        WT[(size_t)n * Kpad + kb + tx] = __float2half(t[tx][ty + i * 8]);
    }
}

__global__ __launch_bounds__(256)
void mega_prep_kernel(const float* __restrict__ f_atoms,
                      const int* __restrict__ mol_ids,
                      const float* __restrict__ W_i,
                      const float* __restrict__ W_h,
                      const float* __restrict__ W_o,
                      const float* __restrict__ W_fi,
                      const float* __restrict__ W_f1)
{
    __shared__ float t[32][33];
    const int b = blockIdx.x;
    const int tid = threadIdx.x;

    if (b < PB_PAD) {
        int idx = b * 256 + tid;
        if (idx < N_ATOMS * KPAD_F) {
            int a = idx / KPAD_F, k = idx - a * KPAD_F;
            g_padAh[idx] = __float2half((k < ATOM_FDIM) ? f_atoms[a * ATOM_FDIM + k] : 0.f);
        }
    } else if (b < PB_WIT) {
        int bi = b - PB_PAD;
        tile_transpose(W_i, g_WiTh, ATOM_FDIM, HIDDEN, KPAD_F,
                       bi % (HIDDEN / 32), bi / (HIDDEN / 32), tid, t);
    } else if (b < PB_WOCAT) {
        int idx = (b - PB_WIT) * 256 + tid;
        int n = idx / K_CAT, k = idx - n * K_CAT;
        float v = 0.f;
        if (k < KPAD_F) {
            if (k < ATOM_FDIM) v = W_o[(size_t)k * HIDDEN + n];
        } else {
            v = W_o[(size_t)(k - KPAD_F + ATOM_FDIM) * HIDDEN + n];
        }
        g_WoCatTh[idx] = __float2half(v);
    } else if (b < PB_WH) {
        int bi = b - PB_WOCAT;
        tile_transpose(W_h, g_WhTh, HIDDEN, HIDDEN, HIDDEN,
                       bi % (HIDDEN / 32), bi / (HIDDEN / 32), tid, t);
    } else if (b < PB_WCOMB) {
        int idx = (b - PB_WH) * 256 + tid;
        int n = idx / HIDDEN, k = idx - n * HIDDEN;
        float v;
        if (n < FFN1)
            v = W_fi[(size_t)k * FFN1 + n] + W_fi[(size_t)(1024 + k) * FFN1 + n];
        else {
            int n2 = n - FFN1;
            v = W_fi[(size_t)k * FFN1 + n2] + W_fi[(size_t)(1536 + k) * FFN1 + n2];
        }
        g_WcombTh[idx] = __float2half(v);
    } else if (b < PB_WM) {
        int bi = b - PB_WCOMB;
        tile_transpose(W_fi + (size_t)512 * FFN1, g_WmTh, HIDDEN, FFN1, HIDDEN,
                       bi % (FFN1 / 32), bi / (FFN1 / 32), tid, t);
    } else if (b < PB_WF1) {
        int bi = b - PB_WM;
        tile_transpose(W_f1, g_Wf1Th, FFN1, FFN2, FFN1,
                       bi % (FFN2 / 32), bi / (FFN2 / 32), tid, t);
    } else {
        int m = (b - PB_WF1) * 256 + tid;
        if (m <= N_MOLS) {
            if (m == N_MOLS) { g_segStart[N_MOLS] = N_ATOMS; return; }
            int lo = 0, hi = N_ATOMS;
            while (lo < hi) {
                int mid = (lo + hi) >> 1;
                if (__ldg(&mol_ids[mid]) < m) lo = mid + 1; else hi = mid;
            }
            g_segStart[m] = lo;
        }
    }
}

// ---------------- neighbor gather-sum (half) --------------------------------
__global__ void gather_sum_h_kernel(const __half* __restrict__ src, int srcStride,
                                    const int* __restrict__ nei,
                                    __half* __restrict__ dst, int relu_src)
{
    int atom = blockIdx.x;
    int c = threadIdx.x;  // 0..63
    const int* nrow = nei + atom * MAX_NEI;
    float2 acc[4] = {{0.f,0.f},{0.f,0.f},{0.f,0.f},{0.f,0.f}};
#pragma unroll
    for (int j = 0; j < MAX_NEI; j++) {
        int n = __ldg(&nrow[j]);
        uint4 v = __ldg((const uint4*)(src + (size_t)n * srcStride) + c);
        uint32_t w[4] = {v.x, v.y, v.z, v.w};
#pragma unroll
        for (int i = 0; i < 4; i++) {
            float2 f = __half22float2(*(__half2*)&w[i]);
            if (relu_src) { f.x = fmaxf(f.x, 0.f); f.y = fmaxf(f.y, 0.f); }
            acc[i].x += f.x; acc[i].y += f.y;
        }
    }
    uint4 o;
    uint32_t* ow = (uint32_t*)&o;
#pragma unroll
    for (int i = 0; i < 4; i++) {
        __half2 h = __floats2half2_rn(acc[i].x, acc[i].y);
        ow[i] = *(uint32_t*)&h;
    }
    ((uint4*)(dst + (size_t)atom * HIDDEN))[c] = o;
}

// ---------------- sorted-segment mean ---------------------------------------
__global__ void seg_reduce_kernel(const __half* __restrict__ ah)
{
    int m = blockIdx.x;
    int col = blockIdx.y * 128 + threadIdx.x;
    int s = __ldg(&g_segStart[m]);
    int e = __ldg(&g_segStart[m + 1]);
    float acc = 0.f;
    for (int r = s; r < e; r++)
        acc += __half2float(__ldg(&ah[(size_t)r * HIDDEN + col]));
    g_sums[(size_t)m * HIDDEN + col] = acc;
    float inv = 1.f / fmaxf((float)(e - s), 1.f);
    g_mvh[(size_t)m * HIDDEN + col] = __float2half(acc * inv);
    if (threadIdx.x == 0 && blockIdx.y == 0) g_cnt[m] = (float)(e - s);
}

// prod[p] = (sums[a]*inv_a)*(sums[b]*inv_b) (half out); also zero g_dot[p]
__global__ void prod_kernel(const int* __restrict__ edges)
{
    int p = blockIdx.x;
    int a = __ldg(&edges[p]);
    int b = __ldg(&edges[N_PAIRS + p]);
    float ia = 1.f / fmaxf(__ldg(&g_cnt[a]), 1.f);
    float ib = 1.f / fmaxf(__ldg(&g_cnt[b]), 1.f);
    int c = threadIdx.x;
    float4 va = __ldg((const float4*)(g_sums + (size_t)a * HIDDEN) + c);
    float4 vb = __ldg((const float4*)(g_sums + (size_t)b * HIDDEN) + c);
    va.x *= ia; va.y *= ia; va.z *= ia; va.w *= ia;
    vb.x *= ib; vb.y *= ib; vb.z *= ib; vb.w *= ib;
    __half2 h0 = __floats2half2_rn(va.x * vb.x, va.y * vb.y);
    __half2 h1 = __floats2half2_rn(va.z * vb.z, va.w * vb.w);
    uint2 o = make_uint2(*(uint32_t*)&h0, *(uint32_t*)&h1);
    ((uint2*)(g_prodh + (size_t)p * HIDDEN))[c] = o;
    if (c == 0) g_dot[p] = 0.f;
}

// out = sigmoid(dot + b_f2)
__global__ void sigmoid_kernel(const float* __restrict__ b2, float* __restrict__ out)
{
    int p = blockIdx.x * blockDim.x + threadIdx.x;
    if (p >= N_PAIRS) return;
    out[p] = 1.f / (1.f + expf(-(g_dot[p] + b2[0])));
}

// ---------------- launch ----------------------------------------------------
extern "C" void kernel_launch(void* const* d_in, const int* in_sizes, int n_in,
                              void* d_out, int out_size)
{
    const float* f_atoms = (const float*)d_in[0];
    const int*   a_nei   = (const int*)d_in[1];
    const int*   mol_ids = (const int*)d_in[2];
    const int*   edges   = (const int*)d_in[3];
    const float* W_i     = (const float*)d_in[4];
    const float* W_h     = (const float*)d_in[5];
    const float* W_o     = (const float*)d_in[6];
    const float* b_o     = (const float*)d_in[7];
    const float* W_fi    = (const float*)d_in[8];
    const float* b_fi    = (const float*)d_in[9];
    const float* W_f1    = (const float*)d_in[10];
    const float* b_f1    = (const float*)d_in[11];
    const float* W_f2    = (const float*)d_in[12];
    const float* b_f2    = (const float*)d_in[13];
    float* out = (float*)d_out;

    __half *padAh, *inph, *bufBh, *bufCh, *h1h, *prodh, *mvh, *Uh;
    __half *wiT, *woCatT, *whT, *wcombT, *wmT, *wf1T;
    float *dotp;
    cudaGetSymbolAddress((void**)&padAh,  g_padAh);
    cudaGetSymbolAddress((void**)&inph,   g_inph);
    cudaGetSymbolAddress((void**)&bufBh,  g_bufBh);
    cudaGetSymbolAddress((void**)&bufCh,  g_bufCh);
    cudaGetSymbolAddress((void**)&h1h,    g_h1h);
    cudaGetSymbolAddress((void**)&prodh,  g_prodh);
    cudaGetSymbolAddress((void**)&mvh,    g_mvh);
    cudaGetSymbolAddress((void**)&Uh,     g_Uh);
    cudaGetSymbolAddress((void**)&wiT,    g_WiTh);
    cudaGetSymbolAddress((void**)&woCatT, g_WoCatTh);
    cudaGetSymbolAddress((void**)&whT,    g_WhTh);
    cudaGetSymbolAddress((void**)&wcombT, g_WcombTh);
    cudaGetSymbolAddress((void**)&wmT,    g_WmTh);
    cudaGetSymbolAddress((void**)&wf1T,   g_Wf1Th);
    cudaGetSymbolAddress((void**)&dotp,   g_dot);

    cudaFuncSetAttribute(hgemm<MODE_N, false, false, false, false, true>,
                         cudaFuncAttributeMaxDynamicSharedMemorySize, SMEM_BYTES);
    cudaFuncSetAttribute(hgemm<MODE_N, true, true, true, false, true>,
                         cudaFuncAttributeMaxDynamicSharedMemorySize, SMEM_BYTES);
    cudaFuncSetAttribute(hgemm<MODE_N, true, false, false, true, true>,
                         cudaFuncAttributeMaxDynamicSharedMemorySize, SMEM_BYTES);
    cudaFuncSetAttribute(hgemm<MODE_PAIR, true, false, false, true, true>,
                         cudaFuncAttributeMaxDynamicSharedMemorySize, SMEM_BYTES);
    cudaFuncSetAttribute(hgemm<MODE_DOT, true, false, false, true, false>,
                         cudaFuncAttributeMaxDynamicSharedMemorySize, SMEM_BYTES);

    const int MT = (N_ATOMS + BM - 1) / BM;  // 782

    // 0. all prep in one launch
    mega_prep_kernel<<<PREP_BLOCKS, 256>>>(f_atoms, mol_ids, W_i, W_h, W_o, W_fi, W_f1);
    // 1. inp = padA @ W_i                                 -> inph [N,512] half
    hgemm<MODE_N, false, false, false, false, true><<<dim3(HIDDEN / BN, MT), 256, SMEM_BYTES>>>(
        N_ATOMS, HIDDEN, KPAD_F, KPAD_F, KPAD_F, KPAD_F, KPAD_F, 0, HIDDEN,
        padAh, padAh, wiT, nullptr, nullptr, inph, nullptr, nullptr);
    // 2. bufBh = sum_j relu(inp[nei])
    gather_sum_h_kernel<<<N_ATOMS, 64>>>(inph, HIDDEN, a_nei, bufBh, 1);
    // 3. msg2 = relu(inp + bufBh @ W_h)                   -> bufCh half
    hgemm<MODE_N, true, true, true, false, true><<<dim3(HIDDEN / BN, MT), 256, SMEM_BYTES>>>(
        N_ATOMS, HIDDEN, HIDDEN, HIDDEN, HIDDEN, HIDDEN, HIDDEN, HIDDEN, HIDDEN,
        bufBh, bufBh, whT, inph, nullptr, bufCh, nullptr, nullptr);
    // 4. bufBh = sum_j msg2[nei]
    gather_sum_h_kernel<<<N_ATOMS, 64>>>(bufCh, HIDDEN, a_nei, bufBh, 0);
    // 6. atom_hiddens = relu([padA | bufBh] @ WoCat + b_o) -> bufCh (split-K)
    hgemm<MODE_N, true, false, false, true, true><<<dim3(HIDDEN / BN, MT), 256, SMEM_BYTES>>>(
        N_ATOMS, HIDDEN, K_CAT, KPAD_F, KPAD_F, HIDDEN, K_CAT, 0, HIDDEN,
        padAh, bufBh, woCatT, nullptr, b_o, bufCh, nullptr, nullptr);
    // 7-8. sorted-segment mean (no atomics): sums, cnt, mvh
    seg_reduce_kernel<<<dim3(N_MOLS, HIDDEN / 128), 128>>>(bufCh);
    // 9a. U = mv @ [(Ws+W1) | (Ws+W2)]                    -> g_Uh [M,4096] half
    hgemm<MODE_N, false, false, false, false, true><<<dim3(4096 / BN, N_MOLS / BM), 256, SMEM_BYTES>>>(
        N_MOLS, 4096, HIDDEN, HIDDEN, HIDDEN, HIDDEN, HIDDEN, 0, 4096,
        mvh, mvh, wcombT, nullptr, nullptr, Uh, nullptr, nullptr);
    // 9b. prod[p] = mv[a]*mv[b] (+ zero dot)              -> prodh half
    prod_kernel<<<N_PAIRS, 128>>>(edges);
    // 10. fused: h1 = relu(prod @ Wm + U1[a] + U2[b] + b_fi) -> h1h half
    hgemm<MODE_PAIR, true, false, false, true, true><<<dim3(FFN1 / BN, N_PAIRS / BM), 256, SMEM_BYTES>>>(
        N_PAIRS, FFN1, HIDDEN, HIDDEN, HIDDEN, HIDDEN, HIDDEN, FFN1, FFN1,
        prodh, prodh, wmT, nullptr, b_fi, h1h, edges, Uh);
    // 11+12a. dot[p] += relu(h1 @ W_f1 + b_f1) . W_f2     (fused dot epilogue)
    hgemm<MODE_DOT, true, false, false, true, false><<<dim3(FFN2 / BN, N_PAIRS / BM), 256, SMEM_BYTES>>>(
        N_PAIRS, FFN2, FFN1, FFN1, FFN1, FFN1, FFN1, 0, FFN2,
        h1h, h1h, wf1T, nullptr, b_f1, dotp, nullptr, W_f2);
    // 12b. out = sigmoid(dot + b_f2)
    sigmoid_kernel<<<(N_PAIRS + 255) / 256, 256>>>(b_f2, out);
}

// round 15
// speedup vs baseline: 1.0647x; 1.0647x over previous
#include <cuda_runtime.h>
#include <cuda_fp16.h>
#include <math.h>
#include <stdint.h>

#define N_ATOMS   100000
#define ATOM_FDIM 133
#define KPAD_F    160
#define HIDDEN    512
#define K_CAT     (KPAD_F + HIDDEN)   // 672
#define MAX_NEI   6
#define N_MOLS    4096
#define N_PAIRS   8192
#define FFN1      2048
#define FFN2      1024

#define MODE_N    0
#define MODE_PAIR 2
#define MODE_DOT  3

// ---------------- scratch (device globals: allocation-free) ----------------
__device__ alignas(16) __half g_padAh [N_ATOMS * KPAD_F];
__device__ alignas(16) __half g_inph  [N_ATOMS * HIDDEN];
__device__ alignas(16) __half g_bufBh [N_ATOMS * HIDDEN];
__device__ alignas(16) __half g_bufCh [N_ATOMS * HIDDEN];
__device__ alignas(16) __half g_h1h   [N_PAIRS * FFN1];
__device__ alignas(16) __half g_prodh [N_PAIRS * HIDDEN];
__device__ alignas(16) __half g_mvh   [N_MOLS * HIDDEN];
__device__ alignas(16) __half g_Uh    [N_MOLS * 4096];
__device__ float g_dot [N_PAIRS];
__device__ float g_sums[N_MOLS * HIDDEN];
__device__ float g_cnt [N_MOLS];
__device__ int   g_segStart[N_MOLS + 1];
// transposed half weights [N][K] (K-contiguous)
__device__ alignas(16) __half g_WiTh   [HIDDEN * KPAD_F];
__device__ alignas(16) __half g_WoCatTh[HIDDEN * K_CAT];
__device__ alignas(16) __half g_WhTh   [HIDDEN * HIDDEN];
__device__ alignas(16) __half g_WcombTh[4096 * HIDDEN];
__device__ alignas(16) __half g_WmTh   [FFN1 * HIDDEN];
__device__ alignas(16) __half g_Wf1Th  [FFN2 * FFN1];

// ---------------- PTX helpers ----------------------------------------------
__device__ __forceinline__ uint32_t smem_u32(const void* p) {
    return (uint32_t)__cvta_generic_to_shared(p);
}
__device__ __forceinline__ void cp16(uint32_t s, const void* g, uint32_t bytes) {
    asm volatile("cp.async.cg.shared.global [%0], [%1], 16, %2;\n"
                 :: "r"(s), "l"(g), "r"(bytes));
}
__device__ __forceinline__ void cp_commit() {
    asm volatile("cp.async.commit_group;\n" ::: "memory");
}
template <int N>
__device__ __forceinline__ void cp_wait() {
    asm volatile("cp.async.wait_group %0;\n" :: "n"(N) : "memory");
}
__device__ __forceinline__ void ldsm4(uint32_t* r, uint32_t addr) {
    asm volatile("ldmatrix.sync.aligned.m8n8.x4.shared.b16 {%0,%1,%2,%3}, [%4];\n"
                 : "=r"(r[0]), "=r"(r[1]), "=r"(r[2]), "=r"(r[3]) : "r"(addr));
}
__device__ __forceinline__ void mma_f16(float* c, const uint32_t* a,
                                        uint32_t b0, uint32_t b1) {
    asm volatile(
        "mma.sync.aligned.m16n8k16.row.col.f32.f16.f16.f32 "
        "{%0,%1,%2,%3}, {%4,%5,%6,%7}, {%8,%9}, {%0,%1,%2,%3};\n"
        : "+f"(c[0]), "+f"(c[1]), "+f"(c[2]), "+f"(c[3])
        : "r"(a[0]), "r"(a[1]), "r"(a[2]), "r"(a[3]), "r"(b0), "r"(b1));
}

// ---------------- GEMM tile config (round-13 proven best) -------------------
#define BM 128
#define BN 128
#define BK 32
#define STAGES 4
#define AT 40
#define A_H (BM * AT)
#define STAGE_H (2 * A_H)
#define STAGE_BYTES (STAGE_H * 2)             // 20480
#define SMEM_BYTES (STAGES * STAGE_BYTES)     // 81920

// ---------------- fp16 mma GEMM: C = [A1|A2][MxK] @ BT[NxK]^T ---------------
template <int MODE, bool RELU, bool ADDC, bool CINH, bool BIAS, bool OUTH>
__global__ __launch_bounds__(256, 2)
void hgemm(int M, int N, int K, int K1, int lda1, int lda2, int ldb,
           int ldcin, int ldc,
           const __half* __restrict__ A1, const __half* __restrict__ A2,
           const __half* __restrict__ BT,
           const void* __restrict__ Cin, const float* __restrict__ bias,
           void* __restrict__ Cout,
           const int* __restrict__ idx, const void* __restrict__ Uv)
{
    extern __shared__ __half sm[];
    const uint32_t sbase = smem_u32(sm);
    const int tid = threadIdx.x;
    const int lane = tid & 31, wid = tid >> 5;
    const int wm = wid & 3, wn = wid >> 2;
    const int gid = lane >> 2, tig = lane & 3;
    const int rowBase = blockIdx.y * BM;
    const int colBase = blockIdx.x * BN;
    const int nk = K / BK;

    const __half* aPtr1[2]; const __half* aPtr2[2];
    uint32_t aSm[2]; uint32_t aBytes[2];
    const __half* bPtr[2]; uint32_t bSm[2];
#pragma unroll
    for (int j = 0; j < 2; j++) {
        int idx2 = tid + j * 256;
        int row = idx2 >> 2, c = idx2 & 3;
        int grow = rowBase + row;
        int crow = grow < M ? grow : 0;
        aPtr1[j]  = A1 + (size_t)crow * lda1 + c * 8;
        aPtr2[j]  = A2 + (size_t)crow * lda2 + c * 8;
        aSm[j]    = sbase + (uint32_t)(row * AT + c * 8) * 2;
        aBytes[j] = grow < M ? 16u : 0u;
        bPtr[j] = BT + (size_t)(colBase + row) * ldb + c * 8;
        bSm[j]  = sbase + (uint32_t)(A_H + row * AT + c * 8) * 2;
    }

    auto load_stage = [&](int stg, int kc0) {
        const uint32_t so = (uint32_t)stg * STAGE_BYTES;
#pragma unroll
        for (int j = 0; j < 2; j++) {
            const __half* src = (kc0 < K1) ? (aPtr1[j] + kc0)
                                           : (aPtr2[j] + (kc0 - K1));
            cp16(aSm[j] + so, src, aBytes[j]);
        }
#pragma unroll
        for (int j = 0; j < 2; j++)
            cp16(bSm[j] + so, bPtr[j] + kc0, 16u);
        cp_commit();
    };

    const int lr = lane & 15, lc = lane >> 4;
    uint32_t aLd[2], bLd[4];
#pragma unroll
    for (int mt = 0; mt < 2; mt++)
        aLd[mt] = sbase + (uint32_t)((wm * 32 + mt * 16 + lr) * AT + lc * 8) * 2;
#pragma unroll
    for (int j = 0; j < 4; j++)
        bLd[j] = sbase + (uint32_t)(A_H + (wn * 64 + j * 16 + lr) * AT + lc * 8) * 2;

    float acc[2][8][4];
#pragma unroll
    for (int mt = 0; mt < 2; mt++)
#pragma unroll
        for (int nt = 0; nt < 8; nt++)
#pragma unroll
            for (int i = 0; i < 4; i++) acc[mt][nt][i] = 0.f;

    load_stage(0, 0);
    if (nk > 1) load_stage(1, BK);
    if (nk > 2) load_stage(2, 2 * BK);

    int buf = 0;
    for (int kt = 0; kt < nk; kt++) {
        if (kt == nk - 1)      cp_wait<0>();
        else if (kt == nk - 2) cp_wait<1>();
        else                   cp_wait<2>();
        __syncthreads();
        if (kt + 3 < nk)
            load_stage((buf + 3) % STAGES, (kt + 3) * BK);

        const uint32_t so = (uint32_t)buf * STAGE_BYTES;
        uint32_t af[2][2][4], bf[2][4][4];
#pragma unroll
        for (int ks = 0; ks < 2; ks++) {
            const uint32_t ko = so + ks * 32;
            ldsm4(af[ks][0], aLd[0] + ko);
            ldsm4(af[ks][1], aLd[1] + ko);
#pragma unroll
            for (int j = 0; j < 4; j++)
                ldsm4(bf[ks][j], bLd[j] + ko);
        }
#pragma unroll
        for (int ks = 0; ks < 2; ks++)
#pragma unroll
            for (int mt = 0; mt < 2; mt++)
#pragma unroll
                for (int j = 0; j < 4; j++) {
                    mma_f16(acc[mt][2 * j],     af[ks][mt], bf[ks][j][0], bf[ks][j][2]);
                    mma_f16(acc[mt][2 * j + 1], af[ks][mt], bf[ks][j][1], bf[ks][j][3]);
                }
        buf = (buf + 1) % STAGES;
    }

    // ---- epilogue ----
#pragma unroll
    for (int mt = 0; mt < 2; mt++) {
#pragma unroll
        for (int h = 0; h < 2; h++) {
            const int row = rowBase + wm * 32 + mt * 16 + gid + h * 8;
            if (row >= M) continue;
            int e0 = 0, e1 = 0;
            if (MODE == MODE_PAIR) { e0 = __ldg(&idx[row]); e1 = __ldg(&idx[N_PAIRS + row]); }
            float dpart = 0.f;
#pragma unroll
            for (int nt = 0; nt < 8; nt++) {
                const int gc = colBase + wn * 64 + nt * 8 + tig * 2;
                float2 v = make_float2(acc[mt][nt][2 * h], acc[mt][nt][2 * h + 1]);
                if (BIAS) {
                    const float2 bb = *(const float2*)(bias + gc);
                    v.x += bb.x; v.y += bb.y;
                }
                if (ADDC) {
                    float2 ci;
                    if (CINH) {
                        __half2 c2 = *(const __half2*)((const __half*)Cin + (size_t)row * ldcin + gc);
                        ci = __half22float2(c2);
                    } else {
                        ci = *(const float2*)((const float*)Cin + (size_t)row * ldcin + gc);
                    }
                    v.x += ci.x; v.y += ci.y;
                }
                if (MODE == MODE_PAIR) {
                    const __half* Uhp = (const __half*)Uv;
                    float2 u1 = __half22float2(*(const __half2*)(Uhp + (size_t)e0 * 4096 + gc));
                    float2 u2 = __half22float2(*(const __half2*)(Uhp + (size_t)e1 * 4096 + FFN1 + gc));
                    v.x += u1.x + u2.x; v.y += u1.y + u2.y;
                }
                if (RELU) { v.x = fmaxf(v.x, 0.f); v.y = fmaxf(v.y, 0.f); }
                if (MODE == MODE_DOT) {
                    const float2 w2 = *(const float2*)((const float*)Uv + gc);
                    dpart += v.x * w2.x + v.y * w2.y;
                } else if (OUTH) {
                    *(__half2*)((__half*)Cout + (size_t)row * ldc + gc) = __floats2half2_rn(v.x, v.y);
                } else {
                    *(float2*)((float*)Cout + (size_t)row * ldc + gc) = v;
                }
            }
            if (MODE == MODE_DOT) {
                dpart += __shfl_xor_sync(0xffffffffu, dpart, 1);
                dpart += __shfl_xor_sync(0xffffffffu, dpart, 2);
                if (tig == 0) atomicAdd((float*)Cout + row, dpart);
            }
        }
    }
}

// ---------------- mega prep: all weight prep + pad + seg bounds, 1 launch ----
// padA vectorized: 8 elems/thread -> blocks = 16M/2048
#define PB_PAD    ((N_ATOMS * KPAD_F) / 2048)                     // 7812.5 -> 7813
#define PB_PAD_N  7813
#define PB_WIT    (PB_PAD_N + (HIDDEN / 32) * (KPAD_F / 32))
#define PB_WOCAT  (PB_WIT + (HIDDEN * K_CAT) / 256)
#define PB_WH     (PB_WOCAT + (HIDDEN / 32) * (HIDDEN / 32))
#define PB_WCOMB  (PB_WH + (4096 * HIDDEN) / 256)
#define PB_WM     (PB_WCOMB + (FFN1 / 32) * (HIDDEN / 32))
#define PB_WF1    (PB_WM + (FFN2 / 32) * (FFN1 / 32))
#define PB_SEG    (PB_WF1 + 17)
#define PREP_BLOCKS PB_SEG

__device__ __forceinline__ void tile_transpose(const float* __restrict__ W,
                                               __half* __restrict__ WT,
                                               int K, int N, int Kpad,
                                               int bx, int by, int tid,
                                               float (*t)[33])
{
    int kb = by * 32, nb = bx * 32;
    int tx = tid & 31, ty = tid >> 5;
#pragma unroll
    for (int i = 0; i < 4; i++) {
        int kk = kb + ty + i * 8;
        t[ty + i * 8][tx] = (kk < K) ? W[(size_t)kk * N + nb + tx] : 0.f;
    }
    __syncthreads();
#pragma unroll
    for (int i = 0; i < 4; i++) {
        int n = nb + ty + i * 8;
        WT[(size_t)n * Kpad + kb + tx] = __float2half(t[tx][ty + i * 8]);
    }
}

__global__ __launch_bounds__(256)
void mega_prep_kernel(const float* __restrict__ f_atoms,
                      const int* __restrict__ mol_ids,
                      const float* __restrict__ W_i,
                      const float* __restrict__ W_h,
                      const float* __restrict__ W_o,
                      const float* __restrict__ W_fi,
                      const float* __restrict__ W_f1)
{
    __shared__ float t[32][33];
    const int b = blockIdx.x;
    const int tid = threadIdx.x;

    if (b < PB_PAD_N) {
        // vectorized pad: each thread fills 8 consecutive padA halves
        int base = (b * 256 + tid) * 8;
        if (base < N_ATOMS * KPAD_F) {
            int a = base / KPAD_F, k = base - a * KPAD_F;   // KPAD_F%8==0 -> same row
            __half2 o[4];
#pragma unroll
            for (int i = 0; i < 4; i++) {
                int k0 = k + 2 * i, k1 = k0 + 1;
                float v0 = (k0 < ATOM_FDIM) ? __ldg(&f_atoms[(size_t)a * ATOM_FDIM + k0]) : 0.f;
                float v1 = (k1 < ATOM_FDIM) ? __ldg(&f_atoms[(size_t)a * ATOM_FDIM + k1]) : 0.f;
                o[i] = __floats2half2_rn(v0, v1);
            }
            *(uint4*)(g_padAh + base) = *(uint4*)o;
        }
    } else if (b < PB_WIT) {
        int bi = b - PB_PAD_N;
        tile_transpose(W_i, g_WiTh, ATOM_FDIM, HIDDEN, KPAD_F,
                       bi % (HIDDEN / 32), bi / (HIDDEN / 32), tid, t);
    } else if (b < PB_WOCAT) {
        int idx = (b - PB_WIT) * 256 + tid;
        int n = idx / K_CAT, k = idx - n * K_CAT;
        float v = 0.f;
        if (k < KPAD_F) {
            if (k < ATOM_FDIM) v = W_o[(size_t)k * HIDDEN + n];
        } else {
            v = W_o[(size_t)(k - KPAD_F + ATOM_FDIM) * HIDDEN + n];
        }
        g_WoCatTh[idx] = __float2half(v);
    } else if (b < PB_WH) {
        int bi = b - PB_WOCAT;
        tile_transpose(W_h, g_WhTh, HIDDEN, HIDDEN, HIDDEN,
                       bi % (HIDDEN / 32), bi / (HIDDEN / 32), tid, t);
    } else if (b < PB_WCOMB) {
        int idx = (b - PB_WH) * 256 + tid;
        int n = idx / HIDDEN, k = idx - n * HIDDEN;
        float v;
        if (n < FFN1)
            v = W_fi[(size_t)k * FFN1 + n] + W_fi[(size_t)(1024 + k) * FFN1 + n];
        else {
            int n2 = n - FFN1;
            v = W_fi[(size_t)k * FFN1 + n2] + W_fi[(size_t)(1536 + k) * FFN1 + n2];
        }
        g_WcombTh[idx] = __float2half(v);
    } else if (b < PB_WM) {
        int bi = b - PB_WCOMB;
        tile_transpose(W_fi + (size_t)512 * FFN1, g_WmTh, HIDDEN, FFN1, HIDDEN,
                       bi % (FFN1 / 32), bi / (FFN1 / 32), tid, t);
    } else if (b < PB_WF1) {
        int bi = b - PB_WM;
        tile_transpose(W_f1, g_Wf1Th, FFN1, FFN2, FFN1,
                       bi % (FFN2 / 32), bi / (FFN2 / 32), tid, t);
    } else {
        int m = (b - PB_WF1) * 256 + tid;
        if (m <= N_MOLS) {
            if (m == N_MOLS) { g_segStart[N_MOLS] = N_ATOMS; return; }
            int lo = 0, hi = N_ATOMS;
            while (lo < hi) {
                int mid = (lo + hi) >> 1;
                if (__ldg(&mol_ids[mid]) < m) lo = mid + 1; else hi = mid;
            }
            g_segStart[m] = lo;
        }
    }
}

// ---------------- neighbor gather-sum (half) --------------------------------
__global__ void gather_sum_h_kernel(const __half* __restrict__ src, int srcStride,
                                    const int* __restrict__ nei,
                                    __half* __restrict__ dst, int relu_src)
{
    int atom = blockIdx.x;
    int c = threadIdx.x;  // 0..63
    const int* nrow = nei + atom * MAX_NEI;
    float2 acc[4] = {{0.f,0.f},{0.f,0.f},{0.f,0.f},{0.f,0.f}};
#pragma unroll
    for (int j = 0; j < MAX_NEI; j++) {
        int n = __ldg(&nrow[j]);
        uint4 v = __ldg((const uint4*)(src + (size_t)n * srcStride) + c);
        uint32_t w[4] = {v.x, v.y, v.z, v.w};
#pragma unroll
        for (int i = 0; i < 4; i++) {
            float2 f = __half22float2(*(__half2*)&w[i]);
            if (relu_src) { f.x = fmaxf(f.x, 0.f); f.y = fmaxf(f.y, 0.f); }
            acc[i].x += f.x; acc[i].y += f.y;
        }
    }
    uint4 o;
    uint32_t* ow = (uint32_t*)&o;
#pragma unroll
    for (int i = 0; i < 4; i++) {
        __half2 h = __floats2half2_rn(acc[i].x, acc[i].y);
        ow[i] = *(uint32_t*)&h;
    }
    ((uint4*)(dst + (size_t)atom * HIDDEN))[c] = o;
}

// ---------------- sorted-segment mean (vectorized) --------------------------
// 128 threads x 4 halves = full 512-col row per block; single blockIdx dim.
__global__ void seg_reduce_kernel(const __half* __restrict__ ah)
{
    int m = blockIdx.x;
    int c4 = threadIdx.x;            // 0..127, covers 4 cols each
    int s = __ldg(&g_segStart[m]);
    int e = __ldg(&g_segStart[m + 1]);
    float2 a0 = {0.f, 0.f}, a1 = {0.f, 0.f};
    for (int r = s; r < e; r++) {
        uint2 v = __ldg((const uint2*)(ah + (size_t)r * HIDDEN) + c4);
        float2 f0 = __half22float2(*(__half2*)&v.x);
        float2 f1 = __half22float2(*(__half2*)&v.y);
        a0.x += f0.x; a0.y += f0.y; a1.x += f1.x; a1.y += f1.y;
    }
    float4* sp = (float4*)(g_sums + (size_t)m * HIDDEN) + c4;
    *sp = make_float4(a0.x, a0.y, a1.x, a1.y);
    float inv = 1.f / fmaxf((float)(e - s), 1.f);
    __half2 h0 = __floats2half2_rn(a0.x * inv, a0.y * inv);
    __half2 h1 = __floats2half2_rn(a1.x * inv, a1.y * inv);
    uint2 o = make_uint2(*(uint32_t*)&h0, *(uint32_t*)&h1);
    ((uint2*)(g_mvh + (size_t)m * HIDDEN))[c4] = o;
    if (c4 == 0) g_cnt[m] = (float)(e - s);
}

// prod[p] = (sums[a]*inv_a)*(sums[b]*inv_b) (half out); also zero g_dot[p]
__global__ void prod_kernel(const int* __restrict__ edges)
{
    int p = blockIdx.x;
    int a = __ldg(&edges[p]);
    int b = __ldg(&edges[N_PAIRS + p]);
    float ia = 1.f / fmaxf(__ldg(&g_cnt[a]), 1.f);
    float ib = 1.f / fmaxf(__ldg(&g_cnt[b]), 1.f);
    int c = threadIdx.x;
    float4 va = __ldg((const float4*)(g_sums + (size_t)a * HIDDEN) + c);
    float4 vb = __ldg((const float4*)(g_sums + (size_t)b * HIDDEN) + c);
    va.x *= ia; va.y *= ia; va.z *= ia; va.w *= ia;
    vb.x *= ib; vb.y *= ib; vb.z *= ib; vb.w *= ib;
    __half2 h0 = __floats2half2_rn(va.x * vb.x, va.y * vb.y);
    __half2 h1 = __floats2half2_rn(va.z * vb.z, va.w * vb.w);
    uint2 o = make_uint2(*(uint32_t*)&h0, *(uint32_t*)&h1);
    ((uint2*)(g_prodh + (size_t)p * HIDDEN))[c] = o;
    if (c == 0) g_dot[p] = 0.f;
}

// out = sigmoid(dot + b_f2)
__global__ void sigmoid_kernel(const float* __restrict__ b2, float* __restrict__ out)
{
    int p = blockIdx.x * blockDim.x + threadIdx.x;
    if (p >= N_PAIRS) return;
    out[p] = 1.f / (1.f + expf(-(g_dot[p] + b2[0])));
}

// ---------------- launch ----------------------------------------------------
extern "C" void kernel_launch(void* const* d_in, const int* in_sizes, int n_in,
                              void* d_out, int out_size)
{
    const float* f_atoms = (const float*)d_in[0];
    const int*   a_nei   = (const int*)d_in[1];
    const int*   mol_ids = (const int*)d_in[2];
    const int*   edges   = (const int*)d_in[3];
    const float* W_i     = (const float*)d_in[4];
    const float* W_h     = (const float*)d_in[5];
    const float* W_o     = (const float*)d_in[6];
    const float* b_o     = (const float*)d_in[7];
    const float* W_fi    = (const float*)d_in[8];
    const float* b_fi    = (const float*)d_in[9];
    const float* W_f1    = (const float*)d_in[10];
    const float* b_f1    = (const float*)d_in[11];
    const float* W_f2    = (const float*)d_in[12];
    const float* b_f2    = (const float*)d_in[13];
    float* out = (float*)d_out;

    __half *padAh, *inph, *bufBh, *bufCh, *h1h, *prodh, *mvh, *Uh;
    __half *wiT, *woCatT, *whT, *wcombT, *wmT, *wf1T;
    float *dotp;
    cudaGetSymbolAddress((void**)&padAh,  g_padAh);
    cudaGetSymbolAddress((void**)&inph,   g_inph);
    cudaGetSymbolAddress((void**)&bufBh,  g_bufBh);
    cudaGetSymbolAddress((void**)&bufCh,  g_bufCh);
    cudaGetSymbolAddress((void**)&h1h,    g_h1h);
    cudaGetSymbolAddress((void**)&prodh,  g_prodh);
    cudaGetSymbolAddress((void**)&mvh,    g_mvh);
    cudaGetSymbolAddress((void**)&Uh,     g_Uh);
    cudaGetSymbolAddress((void**)&wiT,    g_WiTh);
    cudaGetSymbolAddress((void**)&woCatT, g_WoCatTh);
    cudaGetSymbolAddress((void**)&whT,    g_WhTh);
    cudaGetSymbolAddress((void**)&wcombT, g_WcombTh);
    cudaGetSymbolAddress((void**)&wmT,    g_WmTh);
    cudaGetSymbolAddress((void**)&wf1T,   g_Wf1Th);
    cudaGetSymbolAddress((void**)&dotp,   g_dot);

    cudaFuncSetAttribute(hgemm<MODE_N, false, false, false, false, true>,
                         cudaFuncAttributeMaxDynamicSharedMemorySize, SMEM_BYTES);
    cudaFuncSetAttribute(hgemm<MODE_N, true, true, true, false, true>,
                         cudaFuncAttributeMaxDynamicSharedMemorySize, SMEM_BYTES);
    cudaFuncSetAttribute(hgemm<MODE_N, true, false, false, true, true>,
                         cudaFuncAttributeMaxDynamicSharedMemorySize, SMEM_BYTES);
    cudaFuncSetAttribute(hgemm<MODE_PAIR, true, false, false, true, true>,
                         cudaFuncAttributeMaxDynamicSharedMemorySize, SMEM_BYTES);
    cudaFuncSetAttribute(hgemm<MODE_DOT, true, false, false, true, false>,
                         cudaFuncAttributeMaxDynamicSharedMemorySize, SMEM_BYTES);

    const int MT = (N_ATOMS + BM - 1) / BM;  // 782

    // 0. all prep in one launch
    mega_prep_kernel<<<PREP_BLOCKS, 256>>>(f_atoms, mol_ids, W_i, W_h, W_o, W_fi, W_f1);
    // 1. inp = padA @ W_i                                 -> inph [N,512] half
    hgemm<MODE_N, false, false, false, false, true><<<dim3(HIDDEN / BN, MT), 256, SMEM_BYTES>>>(
        N_ATOMS, HIDDEN, KPAD_F, KPAD_F, KPAD_F, KPAD_F, KPAD_F, 0, HIDDEN,
        padAh, padAh, wiT, nullptr, nullptr, inph, nullptr, nullptr);
    // 2. bufBh = sum_j relu(inp[nei])
    gather_sum_h_kernel<<<N_ATOMS, 64>>>(inph, HIDDEN, a_nei, bufBh, 1);
    // 3. msg2 = relu(inp + bufBh @ W_h)                   -> bufCh half
    hgemm<MODE_N, true, true, true, false, true><<<dim3(HIDDEN / BN, MT), 256, SMEM_BYTES>>>(
        N_ATOMS, HIDDEN, HIDDEN, HIDDEN, HIDDEN, HIDDEN, HIDDEN, HIDDEN, HIDDEN,
        bufBh, bufBh, whT, inph, nullptr, bufCh, nullptr, nullptr);
    // 4. bufBh = sum_j msg2[nei]
    gather_sum_h_kernel<<<N_ATOMS, 64>>>(bufCh, HIDDEN, a_nei, bufBh, 0);
    // 6. atom_hiddens = relu([padA | bufBh] @ WoCat + b_o) -> bufCh (split-K)
    hgemm<MODE_N, true, false, false, true, true><<<dim3(HIDDEN / BN, MT), 256, SMEM_BYTES>>>(
        N_ATOMS, HIDDEN, K_CAT, KPAD_F, KPAD_F, HIDDEN, K_CAT, 0, HIDDEN,
        padAh, bufBh, woCatT, nullptr, b_o, bufCh, nullptr, nullptr);
    // 7-8. sorted-segment mean (no atomics): sums, cnt, mvh
    seg_reduce_kernel<<<N_MOLS, 128>>>(bufCh);
    // 9a. U = mv @ [(Ws+W1) | (Ws+W2)]                    -> g_Uh [M,4096] half
    hgemm<MODE_N, false, false, false, false, true><<<dim3(4096 / BN, N_MOLS / BM), 256, SMEM_BYTES>>>(
        N_MOLS, 4096, HIDDEN, HIDDEN, HIDDEN, HIDDEN, HIDDEN, 0, 4096,
        mvh, mvh, wcombT, nullptr, nullptr, Uh, nullptr, nullptr);
    // 9b. prod[p] = mv[a]*mv[b] (+ zero dot)              -> prodh half
    prod_kernel<<<N_PAIRS, 128>>>(edges);
    // 10. fused: h1 = relu(prod @ Wm + U1[a] + U2[b] + b_fi) -> h1h half
    hgemm<MODE_PAIR, true, false, false, true, true><<<dim3(FFN1 / BN, N_PAIRS / BM), 256, SMEM_BYTES>>>(
        N_PAIRS, FFN1, HIDDEN, HIDDEN, HIDDEN, HIDDEN, HIDDEN, FFN1, FFN1,
        prodh, prodh, wmT, nullptr, b_fi, h1h, edges, Uh);
    // 11+12a. dot[p] += relu(h1 @ W_f1 + b_f1) . W_f2     (fused dot epilogue)
    hgemm<MODE_DOT, true, false, false, true, false><<<dim3(FFN2 / BN, N_PAIRS / BM), 256, SMEM_BYTES>>>(
        N_PAIRS, FFN2, FFN1, FFN1, FFN1, FFN1, FFN1, 0, FFN2,
        h1h, h1h, wf1T, nullptr, b_f1, dotp, nullptr, W_f2);
    // 12b. out = sigmoid(dot + b_f2)
    sigmoid_kernel<<<(N_PAIRS + 255) / 256, 256>>>(b_f2, out);
}